// round 3
// baseline (speedup 1.0000x reference)
#include <cuda_runtime.h>

#define NN 100000
#define EE 800000
#define DD 300
#define ETOT (EE + NN)

// ---------------- scratch (static device memory; no allocation) ----------------
__device__ int   g_is64;             // 1 if edge_index is int64, 0 if int32
__device__ int   g_deg[NN];          // out-degree (+1 self loop)
__device__ int   g_cnt[NN];          // in-degree  (+1 self loop)
__device__ int   g_cursor[NN];       // scatter cursors
__device__ int   g_rowptr[NN + 1];   // CSR by destination
__device__ float g_dis[NN];          // deg^-0.5
__device__ int   g_srcv[ETOT];       // CSR: source node per edge
__device__ float g_wv[ETOT];         // CSR: norm per edge
__device__ __align__(16) float g_bufA[(size_t)NN * DD];   // GEMM output
__device__ __align__(16) float g_bufB[(size_t)NN * DD];   // aggregation output (layer 1)

// ---------------- edge dtype detection ----------------
// int64 little-endian values < 2^31 have zero high words at odd u32 positions.
// int32 random edge data has nonzero values there with overwhelming probability.
__global__ void k_detect(const unsigned int* __restrict__ ei32) {
    __shared__ int any;
    if (threadIdx.x == 0) any = 0;
    __syncthreads();
    unsigned v = ei32[2 * threadIdx.x + 1];
    if (v) atomicOr(&any, 1);
    __syncthreads();
    if (threadIdx.x == 0) g_is64 = any ? 0 : 1;
}

__device__ __forceinline__ int load_edge(const void* __restrict__ ei, int idx) {
    if (g_is64) return (int)((const long long*)ei)[idx];
    return ((const int*)ei)[idx];
}

// ---------------- setup kernels ----------------
__global__ void k_init() {
    for (int i = blockIdx.x * blockDim.x + threadIdx.x; i < NN;
         i += gridDim.x * blockDim.x) {
        g_deg[i] = 1;   // self loop
        g_cnt[i] = 1;   // self loop
    }
}

__global__ void k_count(const void* __restrict__ ei) {
    for (int e = blockIdx.x * blockDim.x + threadIdx.x; e < EE;
         e += gridDim.x * blockDim.x) {
        int s = load_edge(ei, e);
        int d = load_edge(ei, EE + e);
        if ((unsigned)s < NN && (unsigned)d < NN) {
            atomicAdd(&g_deg[s], 1);
            atomicAdd(&g_cnt[d], 1);
        }
    }
}

__global__ void k_dis() {
    for (int i = blockIdx.x * blockDim.x + threadIdx.x; i < NN;
         i += gridDim.x * blockDim.x) {
        g_dis[i] = rsqrtf((float)g_deg[i]);
    }
}

// Single-block exclusive scan of g_cnt -> g_rowptr, g_cursor.
__global__ __launch_bounds__(1024) void k_scan() {
    __shared__ int ssum[1024];
    const int t  = threadIdx.x;
    const int CH = (NN + 1023) / 1024;   // 98
    const int base = t * CH;

    int s = 0;
    for (int i = 0; i < CH; i++) {
        int idx = base + i;
        if (idx < NN) s += g_cnt[idx];
    }
    ssum[t] = s;
    __syncthreads();
    // Hillis-Steele inclusive scan
    for (int off = 1; off < 1024; off <<= 1) {
        int v = (t >= off) ? ssum[t - off] : 0;
        __syncthreads();
        ssum[t] += v;
        __syncthreads();
    }
    int run = (t == 0) ? 0 : ssum[t - 1];
    for (int i = 0; i < CH; i++) {
        int idx = base + i;
        if (idx < NN) {
            g_rowptr[idx] = run;
            g_cursor[idx] = run;
            run += g_cnt[idx];
        }
    }
    if (t == 1023) g_rowptr[NN] = ssum[1023];
}

__global__ void k_scatter(const void* __restrict__ ei) {
    for (int e = blockIdx.x * blockDim.x + threadIdx.x; e < ETOT;
         e += gridDim.x * blockDim.x) {
        int s, d;
        if (e < EE) {
            s = load_edge(ei, e);
            d = load_edge(ei, EE + e);
            if ((unsigned)s >= NN || (unsigned)d >= NN) continue;
        } else {
            s = d = e - EE;   // self loop
        }
        int pos = atomicAdd(&g_cursor[d], 1);
        if ((unsigned)pos < ETOT) {
            g_srcv[pos] = s;
            g_wv[pos]   = g_dis[s] * g_dis[d];
        }
    }
}

// ---------------- GEMM: g_bufA[M,300] = A[M,300] @ W[300,300]^T + bias ----------------
// src_flag == 0: A = Aext (external input x); src_flag == 1: A = g_bufB.
// BM=128, BN=64, BK=16, thread tile 8x4, 256 threads.
__global__ __launch_bounds__(256) void k_gemm(const float* __restrict__ Aext,
                                              const float* __restrict__ W,
                                              const float* __restrict__ bias,
                                              int src_flag, int M) {
    const int K = DD, N = DD;
    const float* __restrict__ A = src_flag ? g_bufB : Aext;
    __shared__ float As[16][128];
    __shared__ float Bs[16][64];

    const int tid = threadIdx.x;
    const int bm = blockIdx.x * 128;
    const int bn = blockIdx.y * 64;
    const int tx = tid & 15;   // 0..15 -> col group (4 cols each)
    const int ty = tid >> 4;   // 0..15 -> row group (8 rows each)

    float acc[8][4];
#pragma unroll
    for (int i = 0; i < 8; i++)
#pragma unroll
        for (int j = 0; j < 4; j++) acc[i][j] = 0.0f;

    const int arow = tid >> 1;         // 0..127
    const int ak   = (tid & 1) * 8;    // 0 or 8
    const int brow = tid >> 2;         // 0..63
    const int bk   = (tid & 3) * 4;    // 0,4,8,12

    for (int k0 = 0; k0 < K; k0 += 16) {
        // ---- load A tile (128 x 16), transposed into As[k][m]
#pragma unroll
        for (int h = 0; h < 2; h++) {
            int kk = ak + h * 4;
            float4 v = make_float4(0.f, 0.f, 0.f, 0.f);
            int r = bm + arow;
            if (r < M && (k0 + kk) < K)
                v = *(const float4*)(A + (size_t)r * K + k0 + kk);
            As[kk + 0][arow] = v.x;
            As[kk + 1][arow] = v.y;
            As[kk + 2][arow] = v.z;
            As[kk + 3][arow] = v.w;
        }
        // ---- load B tile (64 x 16) = W[bn..bn+63, k0..k0+15], transposed
        {
            float4 v = make_float4(0.f, 0.f, 0.f, 0.f);
            int r = bn + brow;
            if (r < N && (k0 + bk) < K)
                v = *(const float4*)(W + (size_t)r * K + k0 + bk);
            Bs[bk + 0][brow] = v.x;
            Bs[bk + 1][brow] = v.y;
            Bs[bk + 2][brow] = v.z;
            Bs[bk + 3][brow] = v.w;
        }
        __syncthreads();

#pragma unroll
        for (int k = 0; k < 16; k++) {
            float4 ra0 = *(const float4*)&As[k][ty * 8];
            float4 ra1 = *(const float4*)&As[k][ty * 8 + 4];
            float4 rb  = *(const float4*)&Bs[k][tx * 4];
            float ra[8] = {ra0.x, ra0.y, ra0.z, ra0.w, ra1.x, ra1.y, ra1.z, ra1.w};
            float rn[4] = {rb.x, rb.y, rb.z, rb.w};
#pragma unroll
            for (int i = 0; i < 8; i++)
#pragma unroll
                for (int j = 0; j < 4; j++) acc[i][j] = fmaf(ra[i], rn[j], acc[i][j]);
        }
        __syncthreads();
    }

#pragma unroll
    for (int i = 0; i < 8; i++) {
        int r = bm + ty * 8 + i;
        if (r >= M) continue;
#pragma unroll
        for (int j = 0; j < 4; j++) {
            int c = bn + tx * 4 + j;
            if (c < N) g_bufA[(size_t)r * N + c] = acc[i][j] + bias[c];
        }
    }
}

// ---------------- aggregation: O[c,:] = (relu) sum_e w_e * g_bufA[src_e,:] ----------------
// dst_flag == 0: O = g_bufB (with relu); dst_flag == 1: O = Oext (final output, no relu).
// One block (128 threads) per destination node; dims t, t+128, t+256.
__global__ __launch_bounds__(128) void k_aggregate(float* __restrict__ Oext,
                                                   int dst_flag) {
    const int c = blockIdx.x;
    const int t = threadIdx.x;
    const int beg = g_rowptr[c];
    const int end = g_rowptr[c + 1];

    float a0 = 0.f, a1 = 0.f, a2 = 0.f;
    for (int e = beg; e < end; e++) {
        const int   s = g_srcv[e];
        const float w = g_wv[e];
        const float* hp = g_bufA + (size_t)s * DD;
        a0 += w * hp[t];
        a1 += w * hp[t + 128];
        if (t < DD - 256) a2 += w * hp[t + 256];
    }
    float* op;
    if (dst_flag) {
        op = Oext + (size_t)c * DD;
    } else {
        a0 = fmaxf(a0, 0.f);
        a1 = fmaxf(a1, 0.f);
        a2 = fmaxf(a2, 0.f);
        op = g_bufB + (size_t)c * DD;
    }
    op[t]       = a0;
    op[t + 128] = a1;
    if (t < DD - 256) op[t + 256] = a2;
}

// ---------------- launch ----------------
extern "C" void kernel_launch(void* const* d_in, const int* in_sizes, int n_in,
                              void* d_out, int out_size) {
    const float* x   = (const float*)d_in[0];
    const void*  ei  = d_in[1];              // int32 or int64, detected on device
    const float* W1  = (const float*)d_in[2];
    const float* b1  = (const float*)d_in[3];
    const float* W2  = (const float*)d_in[4];
    const float* b2  = (const float*)d_in[5];
    float*       out = (float*)d_out;

    // graph setup (recomputed every call -> deterministic, graph-capturable)
    k_detect<<<1, 256>>>((const unsigned int*)ei);
    k_init<<<256, 256>>>();
    k_count<<<1024, 256>>>(ei);
    k_dis<<<256, 256>>>();
    k_scan<<<1, 1024>>>();
    k_scatter<<<1024, 256>>>(ei);

    dim3 ggrid((NN + 127) / 128, (DD + 63) / 64);   // 782 x 5

    // layer 1: bufA = x @ W1^T + b1 ; bufB = relu(agg(bufA))
    k_gemm<<<ggrid, 256>>>(x, W1, b1, /*src=*/0, NN);
    k_aggregate<<<NN, 128>>>(out, /*dst=*/0);

    // layer 2: bufA = bufB @ W2^T + b2 ; out = agg(bufA)
    k_gemm<<<ggrid, 256>>>(nullptr, W2, b2, /*src=*/1, NN);
    k_aggregate<<<NN, 128>>>(out, /*dst=*/1);
}

// round 5
// speedup vs baseline: 1.4360x; 1.4360x over previous
#include <cuda_runtime.h>
#include <cuda_bf16.h>
#include <cstdint>

#define NN 100000
#define EE 800000
#define DD 300
#define ETOT (EE + NN)

// bf16 3-term split GEMM packing: A=[hi|lo|hi], B=[hi|hi|lo]
#define SEG 320
#define KP  960           // 3 * SEG
#define KC  64            // K elems per smem chunk
#define NCH (KP / KC)     // 15
#define NPAD 320          // padded N rows for Bpack (2 col-blocks of 160)
#define STR 72            // smem row stride in bf16 elems (144 B)

// ---------------- scratch (static device memory; no allocation) ----------------
__device__ int   g_is64;
__device__ int   g_deg[NN];
__device__ int   g_cnt[NN];
__device__ int   g_cursor[NN];
__device__ int   g_rowptr[NN + 1];
__device__ float g_dis[NN];
__device__ int   g_srcv[ETOT];
__device__ float g_wv[ETOT];
__device__ __align__(16) float g_bufA[(size_t)NN * DD];   // GEMM output
__device__ __align__(16) float g_bufB[(size_t)NN * DD];   // layer-1 agg output
__device__ __align__(16) __nv_bfloat16 g_Apack[(size_t)NN * KP];
__device__ __align__(16) __nv_bfloat16 g_Bpack[(size_t)NPAD * KP];

// ---------------- PTX helpers (baseline ISA only: sm_80-era) ----------------
__device__ __forceinline__ uint32_t smem_u32(const void* p) {
    uint32_t a;
    asm("{ .reg .u64 t; cvta.to.shared.u64 t, %1; cvt.u32.u64 %0, t; }" : "=r"(a) : "l"(p));
    return a;
}
__device__ __forceinline__ void cp16(uint32_t saddr, const void* g, uint32_t sz) {
    asm volatile("cp.async.cg.shared.global [%0], [%1], 16, %2;"
                 :: "r"(saddr), "l"(g), "r"(sz) : "memory");
}
#define CP_COMMIT() asm volatile("cp.async.commit_group;" ::: "memory")
#define CP_WAIT(n)  asm volatile("cp.async.wait_group %0;" :: "n"(n) : "memory")

__device__ __forceinline__ void ldsm_x4(uint32_t& r0, uint32_t& r1, uint32_t& r2,
                                        uint32_t& r3, uint32_t a) {
    asm volatile("ldmatrix.sync.aligned.m8n8.x4.shared.b16 {%0,%1,%2,%3}, [%4];"
                 : "=r"(r0), "=r"(r1), "=r"(r2), "=r"(r3) : "r"(a));
}
__device__ __forceinline__ void ldsm_x2(uint32_t& r0, uint32_t& r1, uint32_t a) {
    asm volatile("ldmatrix.sync.aligned.m8n8.x2.shared.b16 {%0,%1}, [%2];"
                 : "=r"(r0), "=r"(r1) : "r"(a));
}
__device__ __forceinline__ void mma16816(float* c, const uint32_t* a, const uint32_t* b) {
    asm volatile("mma.sync.aligned.m16n8k16.row.col.f32.bf16.bf16.f32 "
                 "{%0,%1,%2,%3}, {%4,%5,%6,%7}, {%8,%9}, {%0,%1,%2,%3};"
                 : "+f"(c[0]), "+f"(c[1]), "+f"(c[2]), "+f"(c[3])
                 : "r"(a[0]), "r"(a[1]), "r"(a[2]), "r"(a[3]), "r"(b[0]), "r"(b[1]));
}

// ---------------- edge dtype detection ----------------
__global__ void k_detect(const unsigned int* __restrict__ ei32) {
    __shared__ int any;
    if (threadIdx.x == 0) any = 0;
    __syncthreads();
    unsigned v = ei32[2 * threadIdx.x + 1];
    if (v) atomicOr(&any, 1);
    __syncthreads();
    if (threadIdx.x == 0) g_is64 = any ? 0 : 1;
}

__device__ __forceinline__ int load_edge(const void* __restrict__ ei, int idx) {
    if (g_is64) return (int)((const long long*)ei)[idx];
    return ((const int*)ei)[idx];
}

// ---------------- setup kernels ----------------
__global__ void k_init() {
    for (int i = blockIdx.x * blockDim.x + threadIdx.x; i < NN;
         i += gridDim.x * blockDim.x) {
        g_deg[i] = 1;
        g_cnt[i] = 1;
    }
}

__global__ void k_count(const void* __restrict__ ei) {
    for (int e = blockIdx.x * blockDim.x + threadIdx.x; e < EE;
         e += gridDim.x * blockDim.x) {
        int s = load_edge(ei, e);
        int d = load_edge(ei, EE + e);
        if ((unsigned)s < NN && (unsigned)d < NN) {
            atomicAdd(&g_deg[s], 1);
            atomicAdd(&g_cnt[d], 1);
        }
    }
}

__global__ void k_dis() {
    for (int i = blockIdx.x * blockDim.x + threadIdx.x; i < NN;
         i += gridDim.x * blockDim.x) {
        g_dis[i] = rsqrtf((float)g_deg[i]);
    }
}

__global__ __launch_bounds__(1024) void k_scan() {
    __shared__ int ssum[1024];
    const int t  = threadIdx.x;
    const int CH = (NN + 1023) / 1024;
    const int base = t * CH;

    int s = 0;
    for (int i = 0; i < CH; i++) {
        int idx = base + i;
        if (idx < NN) s += g_cnt[idx];
    }
    ssum[t] = s;
    __syncthreads();
    for (int off = 1; off < 1024; off <<= 1) {
        int v = (t >= off) ? ssum[t - off] : 0;
        __syncthreads();
        ssum[t] += v;
        __syncthreads();
    }
    int run = (t == 0) ? 0 : ssum[t - 1];
    for (int i = 0; i < CH; i++) {
        int idx = base + i;
        if (idx < NN) {
            g_rowptr[idx] = run;
            g_cursor[idx] = run;
            run += g_cnt[idx];
        }
    }
    if (t == 1023) g_rowptr[NN] = ssum[1023];
}

__global__ void k_scatter(const void* __restrict__ ei) {
    for (int e = blockIdx.x * blockDim.x + threadIdx.x; e < ETOT;
         e += gridDim.x * blockDim.x) {
        int s, d;
        if (e < EE) {
            s = load_edge(ei, e);
            d = load_edge(ei, EE + e);
            if ((unsigned)s >= NN || (unsigned)d >= NN) continue;
        } else {
            s = d = e - EE;
        }
        int pos = atomicAdd(&g_cursor[d], 1);
        if ((unsigned)pos < ETOT) {
            g_srcv[pos] = s;
            g_wv[pos]   = g_dis[s] * g_dis[d];
        }
    }
}

// ---------------- packing ----------------
// A: cols [0,SEG)=hi, [SEG,2SEG)=lo, [2SEG,3SEG)=hi (data in first 300 of each segment)
__global__ void k_packA(const float* __restrict__ xext, int use_internal) {
    const float* __restrict__ src = use_internal ? g_bufB : xext;
    const size_t total = (size_t)NN * SEG;
    for (size_t i = (size_t)blockIdx.x * blockDim.x + threadIdx.x; i < total;
         i += (size_t)gridDim.x * blockDim.x) {
        int row = (int)(i / SEG);
        int c   = (int)(i % SEG);
        __nv_bfloat16* dst = g_Apack + (size_t)row * KP;
        if (c < DD) {
            float v = src[(size_t)row * DD + c];
            __nv_bfloat16 h = __float2bfloat16(v);
            float lo = v - __bfloat162float(h);
            dst[c]           = h;
            dst[SEG + c]     = __float2bfloat16(lo);
            dst[2 * SEG + c] = h;
        } else {
            __nv_bfloat16 z = __float2bfloat16(0.f);
            dst[c] = z; dst[SEG + c] = z; dst[2 * SEG + c] = z;
        }
    }
}

// B: cols [0,SEG)=hi, [SEG,2SEG)=hi, [2SEG,3SEG)=lo ; rows >= 300 zero
__global__ void k_packB(const float* __restrict__ W) {
    const int total = NPAD * KP;
    for (int i = blockIdx.x * blockDim.x + threadIdx.x; i < total;
         i += gridDim.x * blockDim.x) {
        int row = i / KP;
        int k   = i % KP;
        int seg = k / SEG;
        int kk  = k % SEG;
        __nv_bfloat16 out = __float2bfloat16(0.f);
        if (row < DD && kk < DD) {
            float v = W[(size_t)row * DD + kk];
            if (seg < 2) {
                out = __float2bfloat16(v);
            } else {
                __nv_bfloat16 h = __float2bfloat16(v);
                out = __float2bfloat16(v - __bfloat162float(h));
            }
        }
        g_Bpack[i] = out;
    }
}

// ---------------- mma.sync bf16 GEMM ----------------
// g_bufA[M,300] = Apack[M,KP] @ Bpack[NPAD,KP]^T + bias (fp32 accum)
// CTA 128x160, 8 warps (2 M x 4 N), warp tile 64x40; K in 15 chunks of 64,
// double-buffered smem via cp.async.
#define SA_BYTES (128 * STR * 2)     // 18432
#define SB_BYTES (160 * STR * 2)     // 23040
#define SMEM_MMA (2 * SA_BYTES + 2 * SB_BYTES)   // 82944

__global__ void __launch_bounds__(256) k_gemm_mma(const float* __restrict__ bias) {
    extern __shared__ char smem[];
    const uint32_t sb   = smem_u32(smem);
    const int tid  = threadIdx.x;
    const int wid  = tid >> 5;
    const int lane = tid & 31;
    const int wm   = wid & 1;        // 0..1  -> 64-row slab
    const int wn   = wid >> 1;       // 0..3  -> 40-col slab
    const int bm   = blockIdx.x * 128;
    const int bn   = blockIdx.y * 160;

    const uint32_t sA[2] = { sb,            sb + SA_BYTES };
    const uint32_t sB[2] = { sb + 2 * SA_BYTES, sb + 2 * SA_BYTES + SB_BYTES };

    float acc[4][5][4];
#pragma unroll
    for (int i = 0; i < 4; i++)
#pragma unroll
        for (int j = 0; j < 5; j++)
#pragma unroll
            for (int q = 0; q < 4; q++) acc[i][j][q] = 0.f;

    // ---- async load of one K-chunk into buffer b ----
    auto issue = [&](int c, int b) {
        const int k0 = c * KC;
        // A: 128 rows x 64 elems = 1024 x 16B
#pragma unroll
        for (int t = 0; t < 4; t++) {
            int u   = tid + 256 * t;
            int row = u >> 3;
            int kc  = (u & 7) * 8;
            int gr  = bm + row;
            uint32_t sz = (gr < NN) ? 16u : 0u;
            if (gr >= NN) gr = NN - 1;
            cp16(sA[b] + (row * STR + kc) * 2,
                 g_Apack + (size_t)gr * KP + k0 + kc, sz);
        }
        // B: 160 rows x 64 elems = 1280 x 16B
#pragma unroll
        for (int t = 0; t < 5; t++) {
            int u   = tid + 256 * t;
            int row = u >> 3;
            int kc  = (u & 7) * 8;
            cp16(sB[b] + (row * STR + kc) * 2,
                 g_Bpack + (size_t)(bn + row) * KP + k0 + kc, 16u);
        }
        CP_COMMIT();
    };

    issue(0, 0);
    issue(1, 1);

    for (int c = 0; c < NCH; c++) {
        if (c < NCH - 1) CP_WAIT(1); else CP_WAIT(0);
        __syncthreads();

        const int b = c & 1;
        const uint32_t a_base = sA[b];
        const uint32_t b_base = sB[b];

#pragma unroll
        for (int s = 0; s < 4; s++) {
            const int kb = s * 16;
            uint32_t af[4][4];
#pragma unroll
            for (int i = 0; i < 4; i++) {
                uint32_t addr = a_base +
                    ((wm * 64 + i * 16 + (lane & 15)) * STR + kb + (lane >> 4) * 8) * 2;
                ldsm_x4(af[i][0], af[i][1], af[i][2], af[i][3], addr);
            }
            uint32_t bf[5][2];
#pragma unroll
            for (int j = 0; j < 5; j++) {
                uint32_t addr = b_base +
                    ((wn * 40 + j * 8 + (lane & 7)) * STR + kb + ((lane >> 3) & 1) * 8) * 2;
                ldsm_x2(bf[j][0], bf[j][1], addr);
            }
#pragma unroll
            for (int i = 0; i < 4; i++)
#pragma unroll
                for (int j = 0; j < 5; j++)
                    mma16816(acc[i][j], af[i], bf[j]);
        }

        __syncthreads();
        if (c + 2 < NCH) issue(c + 2, b);
    }

    // ---- epilogue: bias + store fp32 ----
    const int mrow = lane >> 2;          // 0..7
    const int ncol = 2 * (lane & 3);     // 0,2,4,6
#pragma unroll
    for (int i = 0; i < 4; i++) {
#pragma unroll
        for (int j = 0; j < 5; j++) {
            int gc = bn + wn * 40 + j * 8 + ncol;
            if (gc >= DD) continue;
            float bx = __ldg(bias + gc);
            float by = __ldg(bias + gc + 1);
            int gr0 = bm + wm * 64 + i * 16 + mrow;
            if (gr0 < NN) {
                float2 v = make_float2(acc[i][j][0] + bx, acc[i][j][1] + by);
                *(float2*)(g_bufA + (size_t)gr0 * DD + gc) = v;
            }
            int gr1 = gr0 + 8;
            if (gr1 < NN) {
                float2 v = make_float2(acc[i][j][2] + bx, acc[i][j][3] + by);
                *(float2*)(g_bufA + (size_t)gr1 * DD + gc) = v;
            }
        }
    }
}

// ---------------- aggregation ----------------
__global__ __launch_bounds__(128) void k_aggregate(float* __restrict__ Oext,
                                                   int dst_flag) {
    const int c = blockIdx.x;
    const int t = threadIdx.x;
    const int beg = g_rowptr[c];
    const int end = g_rowptr[c + 1];

    float a0 = 0.f, a1 = 0.f, a2 = 0.f;
    for (int e = beg; e < end; e++) {
        const int   s = g_srcv[e];
        const float w = g_wv[e];
        const float* hp = g_bufA + (size_t)s * DD;
        a0 += w * hp[t];
        a1 += w * hp[t + 128];
        if (t < DD - 256) a2 += w * hp[t + 256];
    }
    float* op;
    if (dst_flag) {
        op = Oext + (size_t)c * DD;
    } else {
        a0 = fmaxf(a0, 0.f);
        a1 = fmaxf(a1, 0.f);
        a2 = fmaxf(a2, 0.f);
        op = g_bufB + (size_t)c * DD;
    }
    op[t]       = a0;
    op[t + 128] = a1;
    if (t < DD - 256) op[t + 256] = a2;
}

// ---------------- launch ----------------
extern "C" void kernel_launch(void* const* d_in, const int* in_sizes, int n_in,
                              void* d_out, int out_size) {
    const float* x   = (const float*)d_in[0];
    const void*  ei  = d_in[1];
    const float* W1  = (const float*)d_in[2];
    const float* b1  = (const float*)d_in[3];
    const float* W2  = (const float*)d_in[4];
    const float* b2  = (const float*)d_in[5];
    float*       out = (float*)d_out;

    static int smem_set = 0;
    if (!smem_set) {
        cudaFuncSetAttribute(k_gemm_mma, cudaFuncAttributeMaxDynamicSharedMemorySize,
                             SMEM_MMA);
        smem_set = 1;
    }

    // graph setup (deterministic each call)
    k_detect<<<1, 256>>>((const unsigned int*)ei);
    k_init<<<256, 256>>>();
    k_count<<<1024, 256>>>(ei);
    k_dis<<<256, 256>>>();
    k_scan<<<1, 1024>>>();
    k_scatter<<<1024, 256>>>(ei);

    dim3 ggrid((NN + 127) / 128, 2);   // 782 x 2

    // layer 1
    k_packA<<<8192, 256>>>(x, 0);
    k_packB<<<512, 256>>>(W1);
    k_gemm_mma<<<ggrid, 256, SMEM_MMA>>>(b1);
    k_aggregate<<<NN, 128>>>(out, 0);

    // layer 2
    k_packA<<<8192, 256>>>(x, 1);
    k_packB<<<512, 256>>>(W2);
    k_gemm_mma<<<ggrid, 256, SMEM_MMA>>>(b2);
    k_aggregate<<<NN, 128>>>(out, 1);
}

// round 6
// speedup vs baseline: 1.7647x; 1.2289x over previous
#include <cuda_runtime.h>
#include <cstdint>

#define NN 100000
#define EE 800000
#define DD 300
#define ETOT (EE + NN)

// tf32 GEMM config: K padded to 320, chunks of 32
#define KPAD 320
#define KC   32
#define NCH  (KPAD / KC)    // 10
#define STRF 36             // smem row stride in floats (144 B)

// ---------------- scratch (static device memory; no allocation) ----------------
__device__ int   g_is64;
__device__ int   g_deg[NN];
__device__ int   g_cnt[NN];
__device__ int   g_cursor[NN];
__device__ int   g_rowptr[NN + 1];
__device__ float g_dis[NN];
__device__ int   g_srcv[ETOT];
__device__ float g_wv[ETOT];
__device__ __align__(16) float g_bufA[(size_t)NN * DD];   // GEMM output
__device__ __align__(16) float g_bufB[(size_t)NN * DD];   // layer-1 agg output

// ---------------- PTX helpers (baseline sm_80-era ISA only) ----------------
__device__ __forceinline__ uint32_t smem_u32(const void* p) {
    uint32_t a;
    asm("{ .reg .u64 t; cvta.to.shared.u64 t, %1; cvt.u32.u64 %0, t; }" : "=r"(a) : "l"(p));
    return a;
}
__device__ __forceinline__ void cp16(uint32_t saddr, const void* g, uint32_t sz) {
    asm volatile("cp.async.cg.shared.global [%0], [%1], 16, %2;"
                 :: "r"(saddr), "l"(g), "r"(sz) : "memory");
}
#define CP_COMMIT() asm volatile("cp.async.commit_group;" ::: "memory")
#define CP_WAIT(n)  asm volatile("cp.async.wait_group %0;" :: "n"(n) : "memory")

__device__ __forceinline__ void ldsm_x4(uint32_t& r0, uint32_t& r1, uint32_t& r2,
                                        uint32_t& r3, uint32_t a) {
    asm volatile("ldmatrix.sync.aligned.m8n8.x4.shared.b16 {%0,%1,%2,%3}, [%4];"
                 : "=r"(r0), "=r"(r1), "=r"(r2), "=r"(r3) : "r"(a));
}
__device__ __forceinline__ void ldsm_x2(uint32_t& r0, uint32_t& r1, uint32_t a) {
    asm volatile("ldmatrix.sync.aligned.m8n8.x2.shared.b16 {%0,%1}, [%2];"
                 : "=r"(r0), "=r"(r1) : "r"(a));
}
__device__ __forceinline__ void cvt_tf32(uint32_t& x) {
    asm("cvt.rna.tf32.f32 %0, %0;" : "+r"(x));
}
__device__ __forceinline__ void mma_tf32(float* c, const uint32_t* a, const uint32_t* b) {
    asm volatile("mma.sync.aligned.m16n8k8.row.col.f32.tf32.tf32.f32 "
                 "{%0,%1,%2,%3}, {%4,%5,%6,%7}, {%8,%9}, {%0,%1,%2,%3};"
                 : "+f"(c[0]), "+f"(c[1]), "+f"(c[2]), "+f"(c[3])
                 : "r"(a[0]), "r"(a[1]), "r"(a[2]), "r"(a[3]), "r"(b[0]), "r"(b[1]));
}

// ---------------- edge dtype detection ----------------
__global__ void k_detect(const unsigned int* __restrict__ ei32) {
    __shared__ int any;
    if (threadIdx.x == 0) any = 0;
    __syncthreads();
    unsigned v = ei32[2 * threadIdx.x + 1];
    if (v) atomicOr(&any, 1);
    __syncthreads();
    if (threadIdx.x == 0) g_is64 = any ? 0 : 1;
}

__device__ __forceinline__ int load_edge(const void* __restrict__ ei, int idx) {
    if (g_is64) return (int)((const long long*)ei)[idx];
    return ((const int*)ei)[idx];
}

// ---------------- setup kernels ----------------
__global__ void k_init() {
    for (int i = blockIdx.x * blockDim.x + threadIdx.x; i < NN;
         i += gridDim.x * blockDim.x) {
        g_deg[i] = 1;
        g_cnt[i] = 1;
    }
}

__global__ void k_count(const void* __restrict__ ei) {
    for (int e = blockIdx.x * blockDim.x + threadIdx.x; e < EE;
         e += gridDim.x * blockDim.x) {
        int s = load_edge(ei, e);
        int d = load_edge(ei, EE + e);
        if ((unsigned)s < NN && (unsigned)d < NN) {
            atomicAdd(&g_deg[s], 1);
            atomicAdd(&g_cnt[d], 1);
        }
    }
}

__global__ void k_dis() {
    for (int i = blockIdx.x * blockDim.x + threadIdx.x; i < NN;
         i += gridDim.x * blockDim.x) {
        g_dis[i] = rsqrtf((float)g_deg[i]);
    }
}

__global__ __launch_bounds__(1024) void k_scan() {
    __shared__ int ssum[1024];
    const int t  = threadIdx.x;
    const int CH = (NN + 1023) / 1024;
    const int base = t * CH;

    int s = 0;
    for (int i = 0; i < CH; i++) {
        int idx = base + i;
        if (idx < NN) s += g_cnt[idx];
    }
    ssum[t] = s;
    __syncthreads();
    for (int off = 1; off < 1024; off <<= 1) {
        int v = (t >= off) ? ssum[t - off] : 0;
        __syncthreads();
        ssum[t] += v;
        __syncthreads();
    }
    int run = (t == 0) ? 0 : ssum[t - 1];
    for (int i = 0; i < CH; i++) {
        int idx = base + i;
        if (idx < NN) {
            g_rowptr[idx] = run;
            g_cursor[idx] = run;
            run += g_cnt[idx];
        }
    }
    if (t == 1023) g_rowptr[NN] = ssum[1023];
}

__global__ void k_scatter(const void* __restrict__ ei) {
    for (int e = blockIdx.x * blockDim.x + threadIdx.x; e < ETOT;
         e += gridDim.x * blockDim.x) {
        int s, d;
        if (e < EE) {
            s = load_edge(ei, e);
            d = load_edge(ei, EE + e);
            if ((unsigned)s >= NN || (unsigned)d >= NN) continue;
        } else {
            s = d = e - EE;
        }
        int pos = atomicAdd(&g_cursor[d], 1);
        if ((unsigned)pos < ETOT) {
            g_srcv[pos] = s;
            g_wv[pos]   = g_dis[s] * g_dis[d];
        }
    }
}

// ---------------- tf32 mma GEMM ----------------
// g_bufA[M,300] = A[M,300] @ W[300,300]^T + bias (fp32 in/out, tf32 compute)
// CTA 128x160, 8 warps (2 M x 4 N), warp tile 64x40; K in 10 chunks of 32,
// double-buffered smem via cp.async. src_flag: 0 -> Aext (x), 1 -> g_bufB.
#define SA_BYTES (128 * STRF * 4)     // 18432
#define SB_BYTES (160 * STRF * 4)     // 23040
#define SMEM_MMA (2 * SA_BYTES + 2 * SB_BYTES)   // 82944

__global__ void __launch_bounds__(256) k_gemm_tf32(const float* __restrict__ Aext,
                                                   const float* __restrict__ W,
                                                   const float* __restrict__ bias,
                                                   int src_flag) {
    extern __shared__ char smem[];
    const float* __restrict__ A = src_flag ? g_bufB : Aext;
    const uint32_t sb   = smem_u32(smem);
    const int tid  = threadIdx.x;
    const int wid  = tid >> 5;
    const int lane = tid & 31;
    const int wm   = wid & 1;        // 0..1  -> 64-row slab
    const int wn   = wid >> 1;       // 0..3  -> 40-col slab
    const int bm   = blockIdx.x * 128;
    const int bn   = blockIdx.y * 160;

    const uint32_t sA[2] = { sb,                sb + SA_BYTES };
    const uint32_t sB[2] = { sb + 2 * SA_BYTES, sb + 2 * SA_BYTES + SB_BYTES };

    float acc[4][5][4];
#pragma unroll
    for (int i = 0; i < 4; i++)
#pragma unroll
        for (int j = 0; j < 5; j++)
#pragma unroll
            for (int q = 0; q < 4; q++) acc[i][j][q] = 0.f;

    // ---- async load of one K-chunk (32 floats) into buffer b ----
    auto issue = [&](int c, int b) {
        const int k0 = c * KC;
        // A: 128 rows x 32 floats = 1024 x 16B segments (4 per thread)
#pragma unroll
        for (int t = 0; t < 4; t++) {
            int u   = tid + 256 * t;
            int row = u >> 3;
            int kc  = (u & 7) * 4;
            int gr  = bm + row;
            int gk  = k0 + kc;
            uint32_t sz = (gr < NN && gk < DD) ? 16u : 0u;
            if (gr >= NN) gr = NN - 1;
            if (gk >= DD) gk = 0;
            cp16(sA[b] + (row * STRF + kc) * 4,
                 A + (size_t)gr * DD + gk, sz);
        }
        // B: 160 rows x 32 floats = 1280 segments (5 per thread)
#pragma unroll
        for (int t = 0; t < 5; t++) {
            int u   = tid + 256 * t;
            int row = u >> 3;
            int kc  = (u & 7) * 4;
            int gr  = bn + row;
            int gk  = k0 + kc;
            uint32_t sz = (gr < DD && gk < DD) ? 16u : 0u;
            if (gr >= DD) gr = 0;
            if (gk >= DD) gk = 0;
            cp16(sB[b] + (row * STRF + kc) * 4,
                 W + (size_t)gr * DD + gk, sz);
        }
        CP_COMMIT();
    };

    issue(0, 0);
    issue(1, 1);

    for (int c = 0; c < NCH; c++) {
        if (c < NCH - 1) CP_WAIT(1); else CP_WAIT(0);
        __syncthreads();

        const int b = c & 1;
        const uint32_t a_base = sA[b];
        const uint32_t b_base = sB[b];

#pragma unroll
        for (int s = 0; s < 4; s++) {
            const int kb = s * 8;
            // A fragments: ldmatrix.x4 over the b16 view of 16x8 tf32 tiles.
            // lanes 0-15 -> rows 0-15 (k cols 0-3), lanes 16-31 -> same rows, k cols 4-7.
            uint32_t af[4][4];
#pragma unroll
            for (int i = 0; i < 4; i++) {
                uint32_t addr = a_base +
                    ((wm * 64 + i * 16 + (lane & 15)) * STRF + kb + (lane >> 4) * 4) * 4;
                ldsm_x4(af[i][0], af[i][1], af[i][2], af[i][3], addr);
                cvt_tf32(af[i][0]); cvt_tf32(af[i][1]);
                cvt_tf32(af[i][2]); cvt_tf32(af[i][3]);
            }
            // B fragments: ldmatrix.x2, lanes 0-7 rows n0..n0+7 (k 0-3), lanes 8-15 k 4-7.
            uint32_t bf[5][2];
#pragma unroll
            for (int j = 0; j < 5; j++) {
                uint32_t addr = b_base +
                    ((wn * 40 + j * 8 + (lane & 7)) * STRF + kb + ((lane >> 3) & 1) * 4) * 4;
                ldsm_x2(bf[j][0], bf[j][1], addr);
                cvt_tf32(bf[j][0]); cvt_tf32(bf[j][1]);
            }
#pragma unroll
            for (int i = 0; i < 4; i++)
#pragma unroll
                for (int j = 0; j < 5; j++)
                    mma_tf32(acc[i][j], af[i], bf[j]);
        }

        __syncthreads();
        if (c + 2 < NCH) issue(c + 2, b);
    }

    // ---- epilogue: bias + store fp32 ----
    const int mrow = lane >> 2;          // 0..7
    const int ncol = 2 * (lane & 3);     // 0,2,4,6
#pragma unroll
    for (int i = 0; i < 4; i++) {
#pragma unroll
        for (int j = 0; j < 5; j++) {
            int gc = bn + wn * 40 + j * 8 + ncol;
            if (gc >= DD) continue;
            float bx = __ldg(bias + gc);
            float by = __ldg(bias + gc + 1);
            int gr0 = bm + wm * 64 + i * 16 + mrow;
            if (gr0 < NN) {
                float2 v = make_float2(acc[i][j][0] + bx, acc[i][j][1] + by);
                *(float2*)(g_bufA + (size_t)gr0 * DD + gc) = v;
            }
            int gr1 = gr0 + 8;
            if (gr1 < NN) {
                float2 v = make_float2(acc[i][j][2] + bx, acc[i][j][3] + by);
                *(float2*)(g_bufA + (size_t)gr1 * DD + gc) = v;
            }
        }
    }
}

// ---------------- aggregation ----------------
__global__ __launch_bounds__(128) void k_aggregate(float* __restrict__ Oext,
                                                   int dst_flag) {
    const int c = blockIdx.x;
    const int t = threadIdx.x;
    const int beg = g_rowptr[c];
    const int end = g_rowptr[c + 1];

    float a0 = 0.f, a1 = 0.f, a2 = 0.f;
    for (int e = beg; e < end; e++) {
        const int   s = g_srcv[e];
        const float w = g_wv[e];
        const float* hp = g_bufA + (size_t)s * DD;
        a0 += w * hp[t];
        a1 += w * hp[t + 128];
        if (t < DD - 256) a2 += w * hp[t + 256];
    }
    float* op;
    if (dst_flag) {
        op = Oext + (size_t)c * DD;
    } else {
        a0 = fmaxf(a0, 0.f);
        a1 = fmaxf(a1, 0.f);
        a2 = fmaxf(a2, 0.f);
        op = g_bufB + (size_t)c * DD;
    }
    op[t]       = a0;
    op[t + 128] = a1;
    if (t < DD - 256) op[t + 256] = a2;
}

// ---------------- launch ----------------
extern "C" void kernel_launch(void* const* d_in, const int* in_sizes, int n_in,
                              void* d_out, int out_size) {
    const float* x   = (const float*)d_in[0];
    const void*  ei  = d_in[1];
    const float* W1  = (const float*)d_in[2];
    const float* b1  = (const float*)d_in[3];
    const float* W2  = (const float*)d_in[4];
    const float* b2  = (const float*)d_in[5];
    float*       out = (float*)d_out;

    static int smem_set = 0;
    if (!smem_set) {
        cudaFuncSetAttribute(k_gemm_tf32, cudaFuncAttributeMaxDynamicSharedMemorySize,
                             SMEM_MMA);
        smem_set = 1;
    }

    // graph setup (deterministic each call)
    k_detect<<<1, 256>>>((const unsigned int*)ei);
    k_init<<<256, 256>>>();
    k_count<<<1024, 256>>>(ei);
    k_dis<<<256, 256>>>();
    k_scan<<<1, 1024>>>();
    k_scatter<<<1024, 256>>>(ei);

    dim3 ggrid((NN + 127) / 128, 2);   // 782 x 2

    // layer 1: bufA = x @ W1^T + b1 ; bufB = relu(agg(bufA))
    k_gemm_tf32<<<ggrid, 256, SMEM_MMA>>>(x, W1, b1, 0);
    k_aggregate<<<NN, 128>>>(out, 0);

    // layer 2: bufA = bufB @ W2^T + b2 ; out = agg(bufA)
    k_gemm_tf32<<<ggrid, 256, SMEM_MMA>>>(nullptr, W2, b2, 1);
    k_aggregate<<<NN, 128>>>(out, 1);
}